// round 1
// baseline (speedup 1.0000x reference)
#include <cuda_runtime.h>
#include <math.h>

// Problem constants
#define BATCH 4
#define SEQ 2048
#define DMODEL 768
#define NHEADS 12
#define DK 64
#define MTOK (BATCH * SEQ)          // 8192 tokens
#define ATTN_ROWS (BATCH * NHEADS * SEQ)  // 98304 rows of length SEQ

// Scratch buffers (allocation-free contract: __device__ globals)
__device__ float g_Q[MTOK * DMODEL];
__device__ float g_K[MTOK * DMODEL];
__device__ float g_V[MTOK * DMODEL];
__device__ float g_AO[MTOK * DMODEL];

// ---------------------------------------------------------------------------
// Classic 128x128x8 register-tiled SGEMM:  C[M,N] = A[M,K] @ W[K,N] + bias
// 256 threads, 8x8 per-thread microtile. M,N multiples of 128, K multiple of 8.
// ---------------------------------------------------------------------------
#define BM 128
#define BN 128
#define BKK 8

__global__ __launch_bounds__(256) void sgemm_bias_kernel(
    const float* __restrict__ A, const float* __restrict__ W,
    const float* __restrict__ bias, float* __restrict__ C,
    int M, int N, int K)
{
    __shared__ float As[BKK][BM];
    __shared__ float Ws[BKK][BN];

    const int tid = threadIdx.x;
    const int block_row = blockIdx.y * BM;
    const int block_col = blockIdx.x * BN;
    const int tr = tid >> 4;   // 0..15
    const int tc = tid & 15;   // 0..15

    const int arow = tid >> 1, acol = (tid & 1) * 4;   // A tile 128x8
    const int wrow = tid >> 5, wcol = (tid & 31) * 4;  // W tile 8x128

    float acc[8][8];
#pragma unroll
    for (int i = 0; i < 8; i++)
#pragma unroll
        for (int j = 0; j < 8; j++) acc[i][j] = 0.0f;

    for (int k0 = 0; k0 < K; k0 += BKK) {
        float4 a4 = *(const float4*)&A[(size_t)(block_row + arow) * K + k0 + acol];
        As[acol + 0][arow] = a4.x; As[acol + 1][arow] = a4.y;
        As[acol + 2][arow] = a4.z; As[acol + 3][arow] = a4.w;
        *(float4*)&Ws[wrow][wcol] =
            *(const float4*)&W[(size_t)(k0 + wrow) * N + block_col + wcol];
        __syncthreads();
#pragma unroll
        for (int k = 0; k < BKK; k++) {
            float ra[8], rb[8];
#pragma unroll
            for (int i = 0; i < 8; i++) ra[i] = As[k][tr * 8 + i];
#pragma unroll
            for (int j = 0; j < 8; j++) rb[j] = Ws[k][tc * 8 + j];
#pragma unroll
            for (int i = 0; i < 8; i++)
#pragma unroll
                for (int j = 0; j < 8; j++) acc[i][j] = fmaf(ra[i], rb[j], acc[i][j]);
        }
        __syncthreads();
    }

#pragma unroll
    for (int i = 0; i < 8; i++) {
        const int r = block_row + tr * 8 + i;
#pragma unroll
        for (int j = 0; j < 8; j += 4) {
            const int c = block_col + tc * 8 + j;
            float4 v;
            v.x = acc[i][j + 0] + bias[c + 0];
            v.y = acc[i][j + 1] + bias[c + 1];
            v.z = acc[i][j + 2] + bias[c + 2];
            v.w = acc[i][j + 3] + bias[c + 3];
            *(float4*)&C[(size_t)r * N + c] = v;
        }
    }
}

// ---------------------------------------------------------------------------
// scores[bh, i, j] = scale * sum_d Q[b, i, h, d] * K[b, j, h, d]
// Writes RAW scaled scores into the attn output region (softmaxed in place next).
// 128x128 tile per block over (queries, keys), k-dim = DK = 64.
// ---------------------------------------------------------------------------
__global__ __launch_bounds__(256) void scores_kernel(
    const float* __restrict__ Q, const float* __restrict__ Km,
    float* __restrict__ attn)
{
    const int bh = blockIdx.z;
    const int b = bh / NHEADS, h = bh % NHEADS;
    const float* Qb = Q + (size_t)b * SEQ * DMODEL + h * DK;
    const float* Kb = Km + (size_t)b * SEQ * DMODEL + h * DK;
    float* Sout = attn + (size_t)bh * SEQ * SEQ;

    const int block_row = blockIdx.y * BM;
    const int block_col = blockIdx.x * BN;

    __shared__ float Qs[BKK][BM];
    __shared__ float Ks[BKK][BN];

    const int tid = threadIdx.x;
    const int tr = tid >> 4, tc = tid & 15;
    const int arow = tid >> 1, acol = (tid & 1) * 4;

    float acc[8][8];
#pragma unroll
    for (int i = 0; i < 8; i++)
#pragma unroll
        for (int j = 0; j < 8; j++) acc[i][j] = 0.0f;

    for (int k0 = 0; k0 < DK; k0 += BKK) {
        float4 a4 = *(const float4*)&Qb[(size_t)(block_row + arow) * DMODEL + k0 + acol];
        Qs[acol + 0][arow] = a4.x; Qs[acol + 1][arow] = a4.y;
        Qs[acol + 2][arow] = a4.z; Qs[acol + 3][arow] = a4.w;
        float4 b4 = *(const float4*)&Kb[(size_t)(block_col + arow) * DMODEL + k0 + acol];
        Ks[acol + 0][arow] = b4.x; Ks[acol + 1][arow] = b4.y;
        Ks[acol + 2][arow] = b4.z; Ks[acol + 3][arow] = b4.w;
        __syncthreads();
#pragma unroll
        for (int k = 0; k < BKK; k++) {
            float ra[8], rb[8];
#pragma unroll
            for (int i = 0; i < 8; i++) ra[i] = Qs[k][tr * 8 + i];
#pragma unroll
            for (int j = 0; j < 8; j++) rb[j] = Ks[k][tc * 8 + j];
#pragma unroll
            for (int i = 0; i < 8; i++)
#pragma unroll
                for (int j = 0; j < 8; j++) acc[i][j] = fmaf(ra[i], rb[j], acc[i][j]);
        }
        __syncthreads();
    }

    const float scale = 0.125f;  // 1/sqrt(64)
#pragma unroll
    for (int i = 0; i < 8; i++) {
        const int r = block_row + tr * 8 + i;
#pragma unroll
        for (int j = 0; j < 8; j += 4) {
            const int c = block_col + tc * 8 + j;
            float4 v;
            v.x = acc[i][j + 0] * scale;
            v.y = acc[i][j + 1] * scale;
            v.z = acc[i][j + 2] * scale;
            v.w = acc[i][j + 3] * scale;
            *(float4*)&Sout[(size_t)r * SEQ + c] = v;
        }
    }
}

// ---------------------------------------------------------------------------
// In-place row softmax over rows of length SEQ=2048. One 256-thread block/row.
// ---------------------------------------------------------------------------
__device__ __forceinline__ float warpMax(float v) {
#pragma unroll
    for (int o = 16; o > 0; o >>= 1) v = fmaxf(v, __shfl_xor_sync(0xFFFFFFFFu, v, o));
    return v;
}
__device__ __forceinline__ float warpSum(float v) {
#pragma unroll
    for (int o = 16; o > 0; o >>= 1) v += __shfl_xor_sync(0xFFFFFFFFu, v, o);
    return v;
}

__global__ __launch_bounds__(256) void softmax_kernel(float* __restrict__ attn)
{
    float* p = attn + (size_t)blockIdx.x * SEQ;
    const int tid = threadIdx.x;
    __shared__ float sred[32];

    float x[8];
    float m = -INFINITY;
#pragma unroll
    for (int i = 0; i < 8; i++) { x[i] = p[tid + i * 256]; m = fmaxf(m, x[i]); }

    m = warpMax(m);
    if ((tid & 31) == 0) sred[tid >> 5] = m;
    __syncthreads();
    if (tid < 32) {
        float v = (tid < 8) ? sred[tid] : -INFINITY;
        v = warpMax(v);
        if (tid == 0) sred[0] = v;
    }
    __syncthreads();
    m = sred[0];
    __syncthreads();

    float sum = 0.0f;
#pragma unroll
    for (int i = 0; i < 8; i++) { x[i] = __expf(x[i] - m); sum += x[i]; }
    sum = warpSum(sum);
    if ((tid & 31) == 0) sred[tid >> 5] = sum;
    __syncthreads();
    if (tid < 32) {
        float v = (tid < 8) ? sred[tid] : 0.0f;
        v = warpSum(v);
        if (tid == 0) sred[0] = v;
    }
    __syncthreads();
    const float inv = 1.0f / sred[0];
#pragma unroll
    for (int i = 0; i < 8; i++) p[tid + i * 256] = x[i] * inv;
}

// ---------------------------------------------------------------------------
// PV: AO[b, i, h, :] = sum_j attn[bh, i, j] * V[b, j, h, :]
// Per bh: GEMM M=2048, N=64, K=2048. Tile 128x64x8, 256 threads, 8x4 microtile.
// AO stored as [token, DMODEL] so the output projection consumes it directly.
// ---------------------------------------------------------------------------
#define PVBM 128
#define PVBN 64
#define PVBK 8

__global__ __launch_bounds__(256) void pv_kernel(
    const float* __restrict__ attn, const float* __restrict__ V,
    float* __restrict__ AO)
{
    const int bh = blockIdx.z;
    const int b = bh / NHEADS, h = bh % NHEADS;
    const float* P = attn + (size_t)bh * SEQ * SEQ;
    const float* Vb = V + (size_t)b * SEQ * DMODEL + h * DK;
    float* Ob = AO + (size_t)b * SEQ * DMODEL + h * DK;

    const int block_row = blockIdx.y * PVBM;

    __shared__ float Ps[PVBK][PVBM];
    __shared__ float Vs[PVBK][PVBN];

    const int tid = threadIdx.x;
    const int tr = tid >> 4, tc = tid & 15;       // tr: 16 row-groups of 8, tc: 16 col-groups of 4
    const int arow = tid >> 1, acol = (tid & 1) * 4;   // P tile 128x8
    const int vrow = tid >> 5, vcol = (tid & 31) * 2;  // V tile 8x64

    float acc[8][4];
#pragma unroll
    for (int i = 0; i < 8; i++)
#pragma unroll
        for (int j = 0; j < 4; j++) acc[i][j] = 0.0f;

    for (int k0 = 0; k0 < SEQ; k0 += PVBK) {
        float4 a4 = *(const float4*)&P[(size_t)(block_row + arow) * SEQ + k0 + acol];
        Ps[acol + 0][arow] = a4.x; Ps[acol + 1][arow] = a4.y;
        Ps[acol + 2][arow] = a4.z; Ps[acol + 3][arow] = a4.w;
        float2 v2 = *(const float2*)&Vb[(size_t)(k0 + vrow) * DMODEL + vcol];
        Vs[vrow][vcol] = v2.x; Vs[vrow][vcol + 1] = v2.y;
        __syncthreads();
#pragma unroll
        for (int k = 0; k < PVBK; k++) {
            float ra[8], rb[4];
#pragma unroll
            for (int i = 0; i < 8; i++) ra[i] = Ps[k][tr * 8 + i];
#pragma unroll
            for (int j = 0; j < 4; j++) rb[j] = Vs[k][tc * 4 + j];
#pragma unroll
            for (int i = 0; i < 8; i++)
#pragma unroll
                for (int j = 0; j < 4; j++) acc[i][j] = fmaf(ra[i], rb[j], acc[i][j]);
        }
        __syncthreads();
    }

#pragma unroll
    for (int i = 0; i < 8; i++) {
        const int r = block_row + tr * 8 + i;
        float4 o;
        o.x = acc[i][0]; o.y = acc[i][1]; o.z = acc[i][2]; o.w = acc[i][3];
        *(float4*)&Ob[(size_t)r * DMODEL + tc * 4] = o;
    }
}

// ---------------------------------------------------------------------------
// Launch
// ---------------------------------------------------------------------------
extern "C" void kernel_launch(void* const* d_in, const int* in_sizes, int n_in,
                              void* d_out, int out_size)
{
    const float* query = (const float*)d_in[0];
    const float* key   = (const float*)d_in[1];
    const float* value = (const float*)d_in[2];
    const float* Wq = (const float*)d_in[3];
    const float* bq = (const float*)d_in[4];
    const float* Wk = (const float*)d_in[5];
    const float* bk = (const float*)d_in[6];
    const float* Wv = (const float*)d_in[7];
    const float* bv = (const float*)d_in[8];
    const float* Wo = (const float*)d_in[9];
    const float* bo = (const float*)d_in[10];

    float* out  = (float*)d_out;                              // [B,S,D]
    float* attn = out + (size_t)MTOK * DMODEL;                // [B,H,S,S]

    float *Qp, *Kp, *Vp, *AOp;
    cudaGetSymbolAddress((void**)&Qp,  g_Q);
    cudaGetSymbolAddress((void**)&Kp,  g_K);
    cudaGetSymbolAddress((void**)&Vp,  g_V);
    cudaGetSymbolAddress((void**)&AOp, g_AO);

    dim3 gproj(DMODEL / BN, MTOK / BM);  // (6, 64)
    sgemm_bias_kernel<<<gproj, 256>>>(query, Wq, bq, Qp, MTOK, DMODEL, DMODEL);
    sgemm_bias_kernel<<<gproj, 256>>>(key,   Wk, bk, Kp, MTOK, DMODEL, DMODEL);
    sgemm_bias_kernel<<<gproj, 256>>>(value, Wv, bv, Vp, MTOK, DMODEL, DMODEL);

    dim3 gscores(SEQ / BN, SEQ / BM, BATCH * NHEADS);  // (16, 16, 48)
    scores_kernel<<<gscores, 256>>>(Qp, Kp, attn);

    softmax_kernel<<<ATTN_ROWS, 256>>>(attn);

    dim3 gpv(1, SEQ / PVBM, BATCH * NHEADS);  // (1, 16, 48)
    pv_kernel<<<gpv, 256>>>(attn, Vp, AOp);

    sgemm_bias_kernel<<<gproj, 256>>>(AOp, Wo, bo, out, MTOK, DMODEL, DMODEL);
}

// round 4
// speedup vs baseline: 1.0598x; 1.0598x over previous
#include <cuda_runtime.h>
#include <math.h>

#define BATCH 4
#define SEQ 2048
#define DMODEL 768
#define NHEADS 12
#define DK 64
#define MTOK (BATCH * SEQ)                 // 8192
#define ATTN_ROWS (BATCH * NHEADS * SEQ)   // 98304

// Scratch (__device__ globals: allocation-free contract)
__device__ float g_Q[MTOK * DMODEL];
__device__ float g_K[MTOK * DMODEL];
__device__ float g_V[MTOK * DMODEL];
__device__ float g_AO[MTOK * DMODEL];
__device__ unsigned g_rowmax[ATTN_ROWS];

// Monotone float<->uint encoding for atomicMax on arbitrary-sign floats
__device__ __forceinline__ unsigned enc_f(float f) {
    unsigned u = __float_as_uint(f);
    return (u & 0x80000000u) ? ~u : (u | 0x80000000u);
}
__device__ __forceinline__ float dec_f(unsigned u) {
    return (u & 0x80000000u) ? __uint_as_float(u & 0x7fffffffu)
                             : __uint_as_float(~u);
}

__global__ void init_rowmax_kernel(unsigned* rm) {
    int i = blockIdx.x * blockDim.x + threadIdx.x;
    if (i < ATTN_ROWS) rm[i] = 0u;   // smaller than enc of any finite score
}

// ---------------------------------------------------------------------------
// Projection GEMM: C = A[M,K] @ W[K,N] + bias. 128x128x16, double-buffered.
// ---------------------------------------------------------------------------
#define BM 128
#define BN 128
#define BK 16

__global__ __launch_bounds__(256) void sgemm_bias_kernel(
    const float* __restrict__ A, const float* __restrict__ W,
    const float* __restrict__ bias, float* __restrict__ C,
    int M, int N, int K)
{
    __shared__ float As[2][BK][BM];
    __shared__ float Ws[2][BK][BN];

    const int tid = threadIdx.x;
    const int block_row = blockIdx.y * BM;
    const int block_col = blockIdx.x * BN;
    const int tr = tid >> 4, tc = tid & 15;

    // load indices (2 float4 per thread per operand)
    const int i0 = tid, i1 = tid + 256;
    const int ar0 = i0 >> 2, ac0 = (i0 & 3) * 4;
    const int ar1 = i1 >> 2, ac1 = (i1 & 3) * 4;
    const int wr0 = i0 >> 5, wc0 = (i0 & 31) * 4;
    const int wr1 = i1 >> 5, wc1 = (i1 & 31) * 4;

    const float* Arow0 = A + (size_t)(block_row + ar0) * K;
    const float* Arow1 = A + (size_t)(block_row + ar1) * K;
    const float* Wbase = W + block_col;

    float acc[8][8];
#pragma unroll
    for (int i = 0; i < 8; i++)
#pragma unroll
        for (int j = 0; j < 8; j++) acc[i][j] = 0.0f;

    const int nt = K / BK;

    // stage 0 load
    {
        float4 a0 = *(const float4*)&Arow0[ac0];
        float4 a1 = *(const float4*)&Arow1[ac1];
        As[0][ac0 + 0][ar0] = a0.x; As[0][ac0 + 1][ar0] = a0.y;
        As[0][ac0 + 2][ar0] = a0.z; As[0][ac0 + 3][ar0] = a0.w;
        As[0][ac1 + 0][ar1] = a1.x; As[0][ac1 + 1][ar1] = a1.y;
        As[0][ac1 + 2][ar1] = a1.z; As[0][ac1 + 3][ar1] = a1.w;
        *(float4*)&Ws[0][wr0][wc0] = *(const float4*)&Wbase[(size_t)wr0 * N + wc0];
        *(float4*)&Ws[0][wr1][wc1] = *(const float4*)&Wbase[(size_t)wr1 * N + wc1];
    }
    __syncthreads();

    for (int t = 0; t < nt; t++) {
        const int buf = t & 1;
        float4 pa0, pa1, pw0, pw1;
        const bool more = (t + 1 < nt);
        if (more) {
            const int k0 = (t + 1) * BK;
            pa0 = *(const float4*)&Arow0[k0 + ac0];
            pa1 = *(const float4*)&Arow1[k0 + ac1];
            pw0 = *(const float4*)&Wbase[(size_t)(k0 + wr0) * N + wc0];
            pw1 = *(const float4*)&Wbase[(size_t)(k0 + wr1) * N + wc1];
        }
#pragma unroll
        for (int k = 0; k < BK; k++) {
            float4 a0 = *(const float4*)&As[buf][k][tr * 8];
            float4 a1 = *(const float4*)&As[buf][k][tr * 8 + 4];
            float4 b0 = *(const float4*)&Ws[buf][k][tc * 8];
            float4 b1 = *(const float4*)&Ws[buf][k][tc * 8 + 4];
            float ra[8] = {a0.x, a0.y, a0.z, a0.w, a1.x, a1.y, a1.z, a1.w};
            float rb[8] = {b0.x, b0.y, b0.z, b0.w, b1.x, b1.y, b1.z, b1.w};
#pragma unroll
            for (int i = 0; i < 8; i++)
#pragma unroll
                for (int j = 0; j < 8; j++) acc[i][j] = fmaf(ra[i], rb[j], acc[i][j]);
        }
        if (more) {
            const int nb = buf ^ 1;
            As[nb][ac0 + 0][ar0] = pa0.x; As[nb][ac0 + 1][ar0] = pa0.y;
            As[nb][ac0 + 2][ar0] = pa0.z; As[nb][ac0 + 3][ar0] = pa0.w;
            As[nb][ac1 + 0][ar1] = pa1.x; As[nb][ac1 + 1][ar1] = pa1.y;
            As[nb][ac1 + 2][ar1] = pa1.z; As[nb][ac1 + 3][ar1] = pa1.w;
            *(float4*)&Ws[nb][wr0][wc0] = pw0;
            *(float4*)&Ws[nb][wr1][wc1] = pw1;
        }
        __syncthreads();
    }

#pragma unroll
    for (int i = 0; i < 8; i++) {
        const int r = block_row + tr * 8 + i;
#pragma unroll
        for (int j = 0; j < 8; j += 4) {
            const int c = block_col + tc * 8 + j;
            float4 v;
            v.x = acc[i][j + 0] + bias[c + 0];
            v.y = acc[i][j + 1] + bias[c + 1];
            v.z = acc[i][j + 2] + bias[c + 2];
            v.w = acc[i][j + 3] + bias[c + 3];
            *(float4*)&C[(size_t)r * N + c] = v;
        }
    }
}

// ---------------------------------------------------------------------------
// Scores: S[bh,i,j] = scale * <Q_i, K_j>. Whole K-dim (64) held in smem,
// no syncs in mainloop. Epilogue: per-row block max -> global atomicMax.
// Dynamic smem: Qs[64][132] + Ks[64][132]
// ---------------------------------------------------------------------------
#define SPAD 132

__global__ __launch_bounds__(256) void scores_kernel(
    const float* __restrict__ Q, const float* __restrict__ Km,
    float* __restrict__ attn, unsigned* __restrict__ rowmax)
{
    extern __shared__ float sm[];
    float* Qs = sm;                // [64][SPAD]
    float* Ks = sm + 64 * SPAD;    // [64][SPAD]

    const int bh = blockIdx.z;
    const int b = bh / NHEADS, h = bh % NHEADS;
    const float* Qb = Q + (size_t)b * SEQ * DMODEL + h * DK;
    const float* Kb = Km + (size_t)b * SEQ * DMODEL + h * DK;
    float* Sout = attn + (size_t)bh * SEQ * SEQ;
    unsigned* rmb = rowmax + (size_t)bh * SEQ;

    const int block_row = blockIdx.y * 128;
    const int block_col = blockIdx.x * 128;
    const int tid = threadIdx.x;
    const int tr = tid >> 4, tc = tid & 15;

    // Load 128x64 Q and K tiles, transposed to [k][m]
#pragma unroll
    for (int l = 0; l < 8; l++) {
        int idx = tid + l * 256;
        int row = idx >> 4, c4 = (idx & 15) * 4;
        float4 q4 = *(const float4*)&Qb[(size_t)(block_row + row) * DMODEL + c4];
        Qs[(c4 + 0) * SPAD + row] = q4.x; Qs[(c4 + 1) * SPAD + row] = q4.y;
        Qs[(c4 + 2) * SPAD + row] = q4.z; Qs[(c4 + 3) * SPAD + row] = q4.w;
        float4 k4 = *(const float4*)&Kb[(size_t)(block_col + row) * DMODEL + c4];
        Ks[(c4 + 0) * SPAD + row] = k4.x; Ks[(c4 + 1) * SPAD + row] = k4.y;
        Ks[(c4 + 2) * SPAD + row] = k4.z; Ks[(c4 + 3) * SPAD + row] = k4.w;
    }
    __syncthreads();

    float acc[8][8];
#pragma unroll
    for (int i = 0; i < 8; i++)
#pragma unroll
        for (int j = 0; j < 8; j++) acc[i][j] = 0.0f;

    for (int ko = 0; ko < 64; ko += 8) {
#pragma unroll
        for (int ki = 0; ki < 8; ki++) {
            const int k = ko + ki;
            float4 a0 = *(const float4*)&Qs[k * SPAD + tr * 8];
            float4 a1 = *(const float4*)&Qs[k * SPAD + tr * 8 + 4];
            float4 b0 = *(const float4*)&Ks[k * SPAD + tc * 8];
            float4 b1 = *(const float4*)&Ks[k * SPAD + tc * 8 + 4];
            float ra[8] = {a0.x, a0.y, a0.z, a0.w, a1.x, a1.y, a1.z, a1.w};
            float rb[8] = {b0.x, b0.y, b0.z, b0.w, b1.x, b1.y, b1.z, b1.w};
#pragma unroll
            for (int i = 0; i < 8; i++)
#pragma unroll
                for (int j = 0; j < 8; j++) acc[i][j] = fmaf(ra[i], rb[j], acc[i][j]);
        }
    }

    const float scale = 0.125f;  // 1/sqrt(64)
#pragma unroll
    for (int i = 0; i < 8; i++) {
        const int r = block_row + tr * 8 + i;
        float sv[8];
        float rm = -INFINITY;
#pragma unroll
        for (int j = 0; j < 8; j++) { sv[j] = acc[i][j] * scale; rm = fmaxf(rm, sv[j]); }
#pragma unroll
        for (int j = 0; j < 8; j += 4) {
            float4 v; v.x = sv[j]; v.y = sv[j + 1]; v.z = sv[j + 2]; v.w = sv[j + 3];
            *(float4*)&Sout[(size_t)r * SEQ + block_col + tc * 8 + j] = v;
        }
        // reduce max across the 16 threads (tc) sharing this row
#pragma unroll
        for (int off = 1; off < 16; off <<= 1)
            rm = fmaxf(rm, __shfl_xor_sync(0xFFFFFFFFu, rm, off));
        if (tc == 0) atomicMax(&rmb[r], enc_f(rm));
    }
}

// ---------------------------------------------------------------------------
// PV fused with softmax. Block: 128 rows x 64 cols (full head), K=2048.
// Phase A: per-row sum of exp(s - m) (m from global rowmax).
// Phase B: GEMM over k-tiles of 64: normalize P, write attn weights,
//          accumulate P@V.
// Dynamic smem: Ps[64][132] + Vs[64][68] + m_s[128] + inv_s[128]
// ---------------------------------------------------------------------------
#define VPAD 68

__global__ __launch_bounds__(256) void pv_softmax_kernel(
    float* __restrict__ attn, const float* __restrict__ V,
    float* __restrict__ AO, const unsigned* __restrict__ rowmax)
{
    extern __shared__ float sm[];
    float* Ps    = sm;                       // [64][SPAD]
    float* Vs    = sm + 64 * SPAD;           // [64][VPAD]
    float* m_s   = sm + 64 * SPAD + 64 * VPAD;   // [128]
    float* inv_s = m_s + 128;                    // [128]

    const int bh = blockIdx.z;
    const int b = bh / NHEADS, h = bh % NHEADS;
    const int block_row = blockIdx.y * 128;
    float* Sbase = attn + (size_t)bh * SEQ * SEQ + (size_t)block_row * SEQ;
    const float* Vb = V + (size_t)b * SEQ * DMODEL + h * DK;
    float* Ob = AO + (size_t)(b * SEQ + block_row) * DMODEL + h * DK;
    const unsigned* rmb = rowmax + (size_t)bh * SEQ + block_row;

    const int tid = threadIdx.x;
    const int wid = tid >> 5, lane = tid & 31;

    if (tid < 128) m_s[tid] = dec_f(rmb[tid]);
    __syncthreads();

    // Phase A: per-row sum of exp(s - m). Warp w handles rows w*16..w*16+15.
    for (int r0 = 0; r0 < 16; r0++) {
        const int row = wid * 16 + r0;
        const float m = m_s[row];
        const float4* Sr = (const float4*)(Sbase + (size_t)row * SEQ);
        float s = 0.0f;
#pragma unroll 4
        for (int it = 0; it < 16; it++) {
            float4 x = Sr[lane + it * 32];
            s += __expf(x.x - m) + __expf(x.y - m) + __expf(x.z - m) + __expf(x.w - m);
        }
#pragma unroll
        for (int off = 16; off > 0; off >>= 1) s += __shfl_xor_sync(0xFFFFFFFFu, s, off);
        if (lane == 0) inv_s[row] = 1.0f / s;
    }
    __syncthreads();

    const int tr = tid >> 4, tc = tid & 15;
    float acc[8][4];
#pragma unroll
    for (int i = 0; i < 8; i++)
#pragma unroll
        for (int j = 0; j < 4; j++) acc[i][j] = 0.0f;

    for (int k0 = 0; k0 < SEQ; k0 += 64) {
        // load S tile -> normalize -> write attn -> stage transposed in smem
#pragma unroll
        for (int l = 0; l < 8; l++) {
            int idx = tid + l * 256;
            int row = idx >> 4, c4 = (idx & 15) * 4;
            float* sp = Sbase + (size_t)row * SEQ + k0 + c4;
            float4 s4 = *(const float4*)sp;
            const float m = m_s[row], inv = inv_s[row];
            float4 p4;
            p4.x = __expf(s4.x - m) * inv;
            p4.y = __expf(s4.y - m) * inv;
            p4.z = __expf(s4.z - m) * inv;
            p4.w = __expf(s4.w - m) * inv;
            *(float4*)sp = p4;                 // final attention weights
            Ps[(c4 + 0) * SPAD + row] = p4.x;
            Ps[(c4 + 1) * SPAD + row] = p4.y;
            Ps[(c4 + 2) * SPAD + row] = p4.z;
            Ps[(c4 + 3) * SPAD + row] = p4.w;
        }
        // load V tile [64 k-rows][64 cols]
#pragma unroll
        for (int l = 0; l < 4; l++) {
            int idx = tid + l * 256;
            int kr = idx >> 4, c4 = (idx & 15) * 4;
            float4 v4 = *(const float4*)&Vb[(size_t)(k0 + kr) * DMODEL + c4];
            *(float4*)&Vs[kr * VPAD + c4] = v4;
        }
        __syncthreads();

        for (int ko = 0; ko < 64; ko += 8) {
#pragma unroll
            for (int ki = 0; ki < 8; ki++) {
                const int kk = ko + ki;
                float4 a0 = *(const float4*)&Ps[kk * SPAD + tr * 8];
                float4 a1 = *(const float4*)&Ps[kk * SPAD + tr * 8 + 4];
                float4 b0 = *(const float4*)&Vs[kk * VPAD + tc * 4];
                float ra[8] = {a0.x, a0.y, a0.z, a0.w, a1.x, a1.y, a1.z, a1.w};
                float rb[4] = {b0.x, b0.y, b0.z, b0.w};
#pragma unroll
                for (int i = 0; i < 8; i++)
#pragma unroll
                    for (int j = 0; j < 4; j++) acc[i][j] = fmaf(ra[i], rb[j], acc[i][j]);
            }
        }
        __syncthreads();
    }

#pragma unroll
    for (int i = 0; i < 8; i++) {
        float4 o;
        o.x = acc[i][0]; o.y = acc[i][1]; o.z = acc[i][2]; o.w = acc[i][3];
        *(float4*)&Ob[(size_t)(tr * 8 + i) * DMODEL + tc * 4] = o;
    }
}

// ---------------------------------------------------------------------------
extern "C" void kernel_launch(void* const* d_in, const int* in_sizes, int n_in,
                              void* d_out, int out_size)
{
    const float* query = (const float*)d_in[0];
    const float* key   = (const float*)d_in[1];
    const float* value = (const float*)d_in[2];
    const float* Wq = (const float*)d_in[3];
    const float* bq = (const float*)d_in[4];
    const float* Wk = (const float*)d_in[5];
    const float* bk = (const float*)d_in[6];
    const float* Wv = (const float*)d_in[7];
    const float* bv = (const float*)d_in[8];
    const float* Wo = (const float*)d_in[9];
    const float* bo = (const float*)d_in[10];

    float* out  = (float*)d_out;
    float* attn = out + (size_t)MTOK * DMODEL;

    float *Qp, *Kp, *Vp, *AOp;
    unsigned* rmp;
    cudaGetSymbolAddress((void**)&Qp,  g_Q);
    cudaGetSymbolAddress((void**)&Kp,  g_K);
    cudaGetSymbolAddress((void**)&Vp,  g_V);
    cudaGetSymbolAddress((void**)&AOp, g_AO);
    cudaGetSymbolAddress((void**)&rmp, g_rowmax);

    static bool attr_done = false;
    const int scores_smem = 2 * 64 * SPAD * sizeof(float);                 // 67584
    const int pv_smem = (64 * SPAD + 64 * VPAD + 256) * (int)sizeof(float); // 52224
    if (!attr_done) {
        cudaFuncSetAttribute(scores_kernel,
            cudaFuncAttributeMaxDynamicSharedMemorySize, scores_smem);
        cudaFuncSetAttribute(pv_softmax_kernel,
            cudaFuncAttributeMaxDynamicSharedMemorySize, pv_smem);
        attr_done = true;
    }

    init_rowmax_kernel<<<(ATTN_ROWS + 255) / 256, 256>>>(rmp);

    dim3 gproj(DMODEL / BN, MTOK / BM);  // (6, 64)
    sgemm_bias_kernel<<<gproj, 256>>>(query, Wq, bq, Qp, MTOK, DMODEL, DMODEL);
    sgemm_bias_kernel<<<gproj, 256>>>(key,   Wk, bk, Kp, MTOK, DMODEL, DMODEL);
    sgemm_bias_kernel<<<gproj, 256>>>(value, Wv, bv, Vp, MTOK, DMODEL, DMODEL);

    dim3 gscores(SEQ / 128, SEQ / 128, BATCH * NHEADS);  // (16, 16, 48)
    scores_kernel<<<gscores, 256, scores_smem>>>(Qp, Kp, attn, rmp);

    dim3 gpv(1, SEQ / 128, BATCH * NHEADS);  // (1, 16, 48)
    pv_softmax_kernel<<<gpv, 256, pv_smem>>>(attn, Vp, AOp, rmp);

    sgemm_bias_kernel<<<gproj, 256>>>(AOp, Wo, bo, out, MTOK, DMODEL, DMODEL);
}

// round 10
// speedup vs baseline: 1.2833x; 1.2110x over previous
#include <cuda_runtime.h>
#include <cuda_bf16.h>
#include <math.h>

#define BATCH 4
#define SEQ 2048
#define DMODEL 768
#define NHEADS 12
#define DK 64
#define MTOK (BATCH * SEQ)                 // 8192

typedef unsigned int u32;

// Scratch (__device__ globals: allocation-free contract)
__device__ float g_Q[MTOK * DMODEL];
__device__ float g_K[MTOK * DMODEL];
__device__ float g_V[MTOK * DMODEL];
__device__ float g_AO[MTOK * DMODEL];

// ===========================================================================
// Warp-level tensor-core helpers (baseline PTX: sm_80+, compiles for sm_103)
// ===========================================================================
__device__ __forceinline__ u32 smem_u32(const void* p) {
    u32 a;
    asm("{ .reg .u64 t; cvta.to.shared.u64 t, %1; cvt.u32.u64 %0, t; }"
        : "=r"(a) : "l"(p));
    return a;
}

#define LDSM_X4(r0, r1, r2, r3, addr)                                        \
    asm volatile("ldmatrix.sync.aligned.m8n8.x4.shared.b16 {%0,%1,%2,%3}, [%4];" \
        : "=r"(r0), "=r"(r1), "=r"(r2), "=r"(r3) : "r"(addr))

__device__ __forceinline__ void mma_bf16(float* c, const u32* a, u32 b0, u32 b1) {
    asm volatile(
        "mma.sync.aligned.m16n8k16.row.col.f32.bf16.bf16.f32 "
        "{%0,%1,%2,%3}, {%4,%5,%6,%7}, {%8,%9}, {%0,%1,%2,%3};"
        : "+f"(c[0]), "+f"(c[1]), "+f"(c[2]), "+f"(c[3])
        : "r"(a[0]), "r"(a[1]), "r"(a[2]), "r"(a[3]), "r"(b0), "r"(b1));
}

__device__ __forceinline__ u32 pack_bf2(__nv_bfloat16 a, __nv_bfloat16 b) {
    __nv_bfloat162 t; t.x = a; t.y = b;
    return *reinterpret_cast<u32*>(&t);
}
__device__ __forceinline__ void split_f(float x, __nv_bfloat16& h, __nv_bfloat16& l) {
    h = __float2bfloat16(x);
    l = __float2bfloat16(x - __bfloat162float(h));
}

// smem row stride for bf16 tiles (64 data + 8 pad) — keeps ldmatrix 16B-aligned
// and conflict-free (144B row stride -> 4-bank shift per row)
#define TST 72

// ===========================================================================
// Projection GEMM (FFMA path): C = A[M,K] @ W[K,N] + bias. 128x128x16.
// ===========================================================================
#define BM 128
#define BN 128
#define BK 16

__global__ __launch_bounds__(256) void sgemm_bias_kernel(
    const float* __restrict__ A, const float* __restrict__ W,
    const float* __restrict__ bias, float* __restrict__ C,
    int M, int N, int K)
{
    __shared__ float As[2][BK][BM];
    __shared__ float Ws[2][BK][BN];

    const int tid = threadIdx.x;
    const int block_row = blockIdx.y * BM;
    const int block_col = blockIdx.x * BN;
    const int tr = tid >> 4, tc = tid & 15;

    const int i0 = tid, i1 = tid + 256;
    const int ar0 = i0 >> 2, ac0 = (i0 & 3) * 4;
    const int ar1 = i1 >> 2, ac1 = (i1 & 3) * 4;
    const int wr0 = i0 >> 5, wc0 = (i0 & 31) * 4;
    const int wr1 = i1 >> 5, wc1 = (i1 & 31) * 4;

    const float* Arow0 = A + (size_t)(block_row + ar0) * K;
    const float* Arow1 = A + (size_t)(block_row + ar1) * K;
    const float* Wbase = W + block_col;

    float acc[8][8];
#pragma unroll
    for (int i = 0; i < 8; i++)
#pragma unroll
        for (int j = 0; j < 8; j++) acc[i][j] = 0.0f;

    const int nt = K / BK;
    {
        float4 a0 = *(const float4*)&Arow0[ac0];
        float4 a1 = *(const float4*)&Arow1[ac1];
        As[0][ac0 + 0][ar0] = a0.x; As[0][ac0 + 1][ar0] = a0.y;
        As[0][ac0 + 2][ar0] = a0.z; As[0][ac0 + 3][ar0] = a0.w;
        As[0][ac1 + 0][ar1] = a1.x; As[0][ac1 + 1][ar1] = a1.y;
        As[0][ac1 + 2][ar1] = a1.z; As[0][ac1 + 3][ar1] = a1.w;
        *(float4*)&Ws[0][wr0][wc0] = *(const float4*)&Wbase[(size_t)wr0 * N + wc0];
        *(float4*)&Ws[0][wr1][wc1] = *(const float4*)&Wbase[(size_t)wr1 * N + wc1];
    }
    __syncthreads();

    for (int t = 0; t < nt; t++) {
        const int buf = t & 1;
        float4 pa0, pa1, pw0, pw1;
        const bool more = (t + 1 < nt);
        if (more) {
            const int k0 = (t + 1) * BK;
            pa0 = *(const float4*)&Arow0[k0 + ac0];
            pa1 = *(const float4*)&Arow1[k0 + ac1];
            pw0 = *(const float4*)&Wbase[(size_t)(k0 + wr0) * N + wc0];
            pw1 = *(const float4*)&Wbase[(size_t)(k0 + wr1) * N + wc1];
        }
#pragma unroll
        for (int k = 0; k < BK; k++) {
            float4 a0 = *(const float4*)&As[buf][k][tr * 8];
            float4 a1 = *(const float4*)&As[buf][k][tr * 8 + 4];
            float4 b0 = *(const float4*)&Ws[buf][k][tc * 8];
            float4 b1 = *(const float4*)&Ws[buf][k][tc * 8 + 4];
            float ra[8] = {a0.x, a0.y, a0.z, a0.w, a1.x, a1.y, a1.z, a1.w};
            float rb[8] = {b0.x, b0.y, b0.z, b0.w, b1.x, b1.y, b1.z, b1.w};
#pragma unroll
            for (int i = 0; i < 8; i++)
#pragma unroll
                for (int j = 0; j < 8; j++) acc[i][j] = fmaf(ra[i], rb[j], acc[i][j]);
        }
        if (more) {
            const int nb = buf ^ 1;
            As[nb][ac0 + 0][ar0] = pa0.x; As[nb][ac0 + 1][ar0] = pa0.y;
            As[nb][ac0 + 2][ar0] = pa0.z; As[nb][ac0 + 3][ar0] = pa0.w;
            As[nb][ac1 + 0][ar1] = pa1.x; As[nb][ac1 + 1][ar1] = pa1.y;
            As[nb][ac1 + 2][ar1] = pa1.z; As[nb][ac1 + 3][ar1] = pa1.w;
            *(float4*)&Ws[nb][wr0][wc0] = pw0;
            *(float4*)&Ws[nb][wr1][wc1] = pw1;
        }
        __syncthreads();
    }

#pragma unroll
    for (int i = 0; i < 8; i++) {
        const int r = block_row + tr * 8 + i;
#pragma unroll
        for (int j = 0; j < 8; j += 4) {
            const int c = block_col + tc * 8 + j;
            float4 v;
            v.x = acc[i][j + 0] + bias[c + 0];
            v.y = acc[i][j + 1] + bias[c + 1];
            v.z = acc[i][j + 2] + bias[c + 2];
            v.w = acc[i][j + 3] + bias[c + 3];
            *(float4*)&C[(size_t)r * N + c] = v;
        }
    }
}

// ===========================================================================
// Scores via HMMA: E[bh,i,j] = exp( <Q_i,K_j> / 8 )  (unnormalized weights)
// 256 threads, 128x128 tile. Warp grid 4(m) x 2(n); warp tile 32x64.
// bf16 hi/lo split, 3 mma products, fp32 accum.
// smem: Qh/Ql/Kh/Kl each [128][TST] bf16 (18432 B) -> 73728 B total.
// ===========================================================================
#define SC_QH 0
#define SC_QL 18432
#define SC_KH 36864
#define SC_KL 55296
#define SC_SMEM 73728

__global__ __launch_bounds__(256) void scores_tc_kernel(
    const float* __restrict__ Q, const float* __restrict__ Km,
    float* __restrict__ attn)
{
    extern __shared__ char sm[];
    const u32 sb = smem_u32(sm);

    const int bh = blockIdx.z;
    const int b = bh / NHEADS, h = bh % NHEADS;
    const float* Qb = Q + (size_t)b * SEQ * DMODEL + h * DK;
    const float* Kb = Km + (size_t)b * SEQ * DMODEL + h * DK;
    float* Sout = attn + (size_t)bh * SEQ * SEQ;

    const int block_row = blockIdx.y * 128;
    const int block_col = blockIdx.x * 128;
    const int tid = threadIdx.x;
    const int wid = tid >> 5, lane = tid & 31;
    const int wm = wid & 3, wn = wid >> 2;

    // Load + split-convert Q,K tiles (128x64 each)
#pragma unroll
    for (int it = 0; it < 8; it++) {
        const int fid = tid + it * 256;
        const int row = fid >> 4, c4 = (fid & 15) * 4;
        const u32 boff = (u32)(row * TST + c4) * 2;

        float4 q = *(const float4*)&Qb[(size_t)(block_row + row) * DMODEL + c4];
        __nv_bfloat16 h0, l0, h1, l1, h2, l2, h3, l3;
        split_f(q.x, h0, l0); split_f(q.y, h1, l1);
        split_f(q.z, h2, l2); split_f(q.w, h3, l3);
        *(u32*)(sm + SC_QH + boff)     = pack_bf2(h0, h1);
        *(u32*)(sm + SC_QH + boff + 4) = pack_bf2(h2, h3);
        *(u32*)(sm + SC_QL + boff)     = pack_bf2(l0, l1);
        *(u32*)(sm + SC_QL + boff + 4) = pack_bf2(l2, l3);

        float4 k = *(const float4*)&Kb[(size_t)(block_col + row) * DMODEL + c4];
        split_f(k.x, h0, l0); split_f(k.y, h1, l1);
        split_f(k.z, h2, l2); split_f(k.w, h3, l3);
        *(u32*)(sm + SC_KH + boff)     = pack_bf2(h0, h1);
        *(u32*)(sm + SC_KH + boff + 4) = pack_bf2(h2, h3);
        *(u32*)(sm + SC_KL + boff)     = pack_bf2(l0, l1);
        *(u32*)(sm + SC_KL + boff + 4) = pack_bf2(l2, l3);
    }
    __syncthreads();

    float acc[2][8][4];
#pragma unroll
    for (int mi = 0; mi < 2; mi++)
#pragma unroll
        for (int ni = 0; ni < 8; ni++)
#pragma unroll
            for (int j = 0; j < 4; j++) acc[mi][ni][j] = 0.0f;

    const int lrow = lane & 15, lhalf = lane >> 4;

#pragma unroll
    for (int ks = 0; ks < 4; ks++) {
        const u32 kcol = (u32)(ks * 16 + lhalf * 8);
        u32 ah[2][4], al[2][4];
#pragma unroll
        for (int mi = 0; mi < 2; mi++) {
            const u32 ro = (u32)((wm * 32 + mi * 16 + lrow) * TST);
            u32 ad = sb + SC_QH + (ro + kcol) * 2;
            LDSM_X4(ah[mi][0], ah[mi][1], ah[mi][2], ah[mi][3], ad);
            ad = sb + SC_QL + (ro + kcol) * 2;
            LDSM_X4(al[mi][0], al[mi][1], al[mi][2], al[mi][3], ad);
        }
        u32 bhf[4][4], blf[4][4];
#pragma unroll
        for (int np = 0; np < 4; np++) {
            const u32 ro = (u32)((wn * 64 + np * 16 + lrow) * TST);
            u32 bd = sb + SC_KH + (ro + kcol) * 2;
            LDSM_X4(bhf[np][0], bhf[np][1], bhf[np][2], bhf[np][3], bd);
            bd = sb + SC_KL + (ro + kcol) * 2;
            LDSM_X4(blf[np][0], blf[np][1], blf[np][2], blf[np][3], bd);
        }
#pragma unroll
        for (int mi = 0; mi < 2; mi++)
#pragma unroll
            for (int np = 0; np < 4; np++)
#pragma unroll
                for (int sub = 0; sub < 2; sub++) {
                    const int ni = np * 2 + sub;
                    mma_bf16(acc[mi][ni], ah[mi], bhf[np][sub], bhf[np][sub + 2]);
                    mma_bf16(acc[mi][ni], ah[mi], blf[np][sub], blf[np][sub + 2]);
                    mma_bf16(acc[mi][ni], al[mi], bhf[np][sub], bhf[np][sub + 2]);
                }
    }

    // Epilogue: exp(s/8), direct float2 stores
    const float scale = 0.125f;
    const int rbase = block_row + wm * 32 + (lane >> 2);
    const int cbase = block_col + wn * 64 + (lane & 3) * 2;
#pragma unroll
    for (int mi = 0; mi < 2; mi++)
#pragma unroll
        for (int half = 0; half < 2; half++) {
            const int r = rbase + mi * 16 + half * 8;
            float* rowp = Sout + (size_t)r * SEQ;
#pragma unroll
            for (int ni = 0; ni < 8; ni++) {
                float2 e;
                e.x = __expf(scale * acc[mi][ni][half * 2]);
                e.y = __expf(scale * acc[mi][ni][half * 2 + 1]);
                *(float2*)&rowp[cbase + ni * 8] = e;
            }
        }
}

// ===========================================================================
// PV via HMMA, fused softmax-normalize.
// Phase A: per-row sums of E -> inv. Phase B: per 64-k tile: P = E*inv
// (written back = final attn weights), split, HMMA accumulate O.
// 256 threads; warp grid 4(m) x 2(n); warp tile 32x32.
// smem: Ph/Pl [128][TST] (18432 ea), Vth/Vtl [64][TST] (9216 ea), inv[128]
// ===========================================================================
#define PV_PH 0
#define PV_PL 18432
#define PV_VTH 36864
#define PV_VTL 46080
#define PV_INV 55296
#define PV_SMEM (55296 + 512)

__global__ __launch_bounds__(256) void pv_tc_kernel(
    float* __restrict__ attn, const float* __restrict__ V,
    float* __restrict__ AO)
{
    extern __shared__ char sm[];
    const u32 sb = smem_u32(sm);
    float* inv_s = (float*)(sm + PV_INV);

    const int bh = blockIdx.z;
    const int b = bh / NHEADS, h = bh % NHEADS;
    const int block_row = blockIdx.y * 128;
    float* Sbase = attn + (size_t)bh * SEQ * SEQ + (size_t)block_row * SEQ;
    const float* Vb = V + (size_t)b * SEQ * DMODEL + h * DK;
    float* Ob = AO + (size_t)(b * SEQ + block_row) * DMODEL + h * DK;

    const int tid = threadIdx.x;
    const int wid = tid >> 5, lane = tid & 31;
    const int wm = wid & 3, wn = wid >> 2;

    // Phase A: row sums of E (warp w: rows w*16 .. w*16+15)
    for (int r0 = 0; r0 < 16; r0++) {
        const int row = wid * 16 + r0;
        const float4* Sr = (const float4*)(Sbase + (size_t)row * SEQ);
        float s = 0.0f;
#pragma unroll 4
        for (int it = 0; it < 16; it++) {
            float4 x = Sr[lane + it * 32];
            s += x.x + x.y + x.z + x.w;
        }
#pragma unroll
        for (int off = 16; off > 0; off >>= 1)
            s += __shfl_xor_sync(0xFFFFFFFFu, s, off);
        if (lane == 0) inv_s[row] = 1.0f / s;
    }
    __syncthreads();

    float acc[2][4][4];
#pragma unroll
    for (int mi = 0; mi < 2; mi++)
#pragma unroll
        for (int ni = 0; ni < 4; ni++)
#pragma unroll
            for (int j = 0; j < 4; j++) acc[mi][ni][j] = 0.0f;

    const int lrow = lane & 15, lhalf = lane >> 4;

    for (int t = 0; t < 32; t++) {
        const int k0 = t * 64;

        // P tile: normalize E, write back attn weights, split
#pragma unroll
        for (int l = 0; l < 8; l++) {
            const int fid = tid + l * 256;
            const int row = fid >> 4, c4 = (fid & 15) * 4;
            float* sp = Sbase + (size_t)row * SEQ + k0 + c4;
            float4 e = *(const float4*)sp;
            const float inv = inv_s[row];
            e.x *= inv; e.y *= inv; e.z *= inv; e.w *= inv;
            *(float4*)sp = e;
            __nv_bfloat16 h0, l0, h1, l1, h2, l2, h3, l3;
            split_f(e.x, h0, l0); split_f(e.y, h1, l1);
            split_f(e.z, h2, l2); split_f(e.w, h3, l3);
            const u32 boff = (u32)(row * TST + c4) * 2;
            *(u32*)(sm + PV_PH + boff)     = pack_bf2(h0, h1);
            *(u32*)(sm + PV_PH + boff + 4) = pack_bf2(h2, h3);
            *(u32*)(sm + PV_PL + boff)     = pack_bf2(l0, l1);
            *(u32*)(sm + PV_PL + boff + 4) = pack_bf2(l2, l3);
        }
        // V tile [64 k][64 n] -> transposed [n][k]
#pragma unroll
        for (int l = 0; l < 4; l++) {
            const int fid = tid + l * 256;
            const int kr = fid >> 4, n4 = (fid & 15) * 4;
            float4 v = *(const float4*)&Vb[(size_t)(k0 + kr) * DMODEL + n4];
            float vv[4] = {v.x, v.y, v.z, v.w};
#pragma unroll
            for (int e = 0; e < 4; e++) {
                __nv_bfloat16 hh, ll;
                split_f(vv[e], hh, ll);
                const u32 boff = (u32)((n4 + e) * TST + kr) * 2;
                *(__nv_bfloat16*)(sm + PV_VTH + boff) = hh;
                *(__nv_bfloat16*)(sm + PV_VTL + boff) = ll;
            }
        }
        __syncthreads();

#pragma unroll
        for (int ks = 0; ks < 4; ks++) {
            const u32 kcol = (u32)(ks * 16 + lhalf * 8);
            u32 ah[2][4], al[2][4];
#pragma unroll
            for (int mi = 0; mi < 2; mi++) {
                const u32 ro = (u32)((wm * 32 + mi * 16 + lrow) * TST);
                u32 ad = sb + PV_PH + (ro + kcol) * 2;
                LDSM_X4(ah[mi][0], ah[mi][1], ah[mi][2], ah[mi][3], ad);
                ad = sb + PV_PL + (ro + kcol) * 2;
                LDSM_X4(al[mi][0], al[mi][1], al[mi][2], al[mi][3], ad);
            }
            u32 bhf[2][4], blf[2][4];
#pragma unroll
            for (int np = 0; np < 2; np++) {
                const u32 ro = (u32)((wn * 32 + np * 16 + lrow) * TST);
                u32 bd = sb + PV_VTH + (ro + kcol) * 2;
                LDSM_X4(bhf[np][0], bhf[np][1], bhf[np][2], bhf[np][3], bd);
                bd = sb + PV_VTL + (ro + kcol) * 2;
                LDSM_X4(blf[np][0], blf[np][1], blf[np][2], blf[np][3], bd);
            }
#pragma unroll
            for (int mi = 0; mi < 2; mi++)
#pragma unroll
                for (int np = 0; np < 2; np++)
#pragma unroll
                    for (int sub = 0; sub < 2; sub++) {
                        const int ni = np * 2 + sub;
                        mma_bf16(acc[mi][ni], ah[mi], bhf[np][sub], bhf[np][sub + 2]);
                        mma_bf16(acc[mi][ni], ah[mi], blf[np][sub], blf[np][sub + 2]);
                        mma_bf16(acc[mi][ni], al[mi], bhf[np][sub], bhf[np][sub + 2]);
                    }
        }
        __syncthreads();
    }

    // Epilogue: store O (128 x 64)
    const int rbase = wm * 32 + (lane >> 2);
    const int cbase = wn * 32 + (lane & 3) * 2;
#pragma unroll
    for (int mi = 0; mi < 2; mi++)
#pragma unroll
        for (int half = 0; half < 2; half++) {
            const int r = rbase + mi * 16 + half * 8;
            float* orow = Ob + (size_t)r * DMODEL;
#pragma unroll
            for (int ni = 0; ni < 4; ni++) {
                float2 o;
                o.x = acc[mi][ni][half * 2];
                o.y = acc[mi][ni][half * 2 + 1];
                *(float2*)&orow[cbase + ni * 8] = o;
            }
        }
}

// ===========================================================================
extern "C" void kernel_launch(void* const* d_in, const int* in_sizes, int n_in,
                              void* d_out, int out_size)
{
    const float* query = (const float*)d_in[0];
    const float* key   = (const float*)d_in[1];
    const float* value = (const float*)d_in[2];
    const float* Wq = (const float*)d_in[3];
    const float* bq = (const float*)d_in[4];
    const float* Wk = (const float*)d_in[5];
    const float* bk = (const float*)d_in[6];
    const float* Wv = (const float*)d_in[7];
    const float* bv = (const float*)d_in[8];
    const float* Wo = (const float*)d_in[9];
    const float* bo = (const float*)d_in[10];

    float* out  = (float*)d_out;
    float* attn = out + (size_t)MTOK * DMODEL;

    float *Qp, *Kp, *Vp, *AOp;
    cudaGetSymbolAddress((void**)&Qp,  g_Q);
    cudaGetSymbolAddress((void**)&Kp,  g_K);
    cudaGetSymbolAddress((void**)&Vp,  g_V);
    cudaGetSymbolAddress((void**)&AOp, g_AO);

    static bool attr_done = false;
    if (!attr_done) {
        cudaFuncSetAttribute(scores_tc_kernel,
            cudaFuncAttributeMaxDynamicSharedMemorySize, SC_SMEM);
        cudaFuncSetAttribute(pv_tc_kernel,
            cudaFuncAttributeMaxDynamicSharedMemorySize, PV_SMEM);
        attr_done = true;
    }

    dim3 gproj(DMODEL / BN, MTOK / BM);  // (6, 64)
    sgemm_bias_kernel<<<gproj, 256>>>(query, Wq, bq, Qp, MTOK, DMODEL, DMODEL);
    sgemm_bias_kernel<<<gproj, 256>>>(key,   Wk, bk, Kp, MTOK, DMODEL, DMODEL);
    sgemm_bias_kernel<<<gproj, 256>>>(value, Wv, bv, Vp, MTOK, DMODEL, DMODEL);

    dim3 gscores(SEQ / 128, SEQ / 128, BATCH * NHEADS);  // (16, 16, 48)
    scores_tc_kernel<<<gscores, 256, SC_SMEM>>>(Qp, Kp, attn);

    dim3 gpv(1, SEQ / 128, BATCH * NHEADS);  // (1, 16, 48)
    pv_tc_kernel<<<gpv, 256, PV_SMEM>>>(attn, Vp, AOp);

    sgemm_bias_kernel<<<gproj, 256>>>(AOp, Wo, bo, out, MTOK, DMODEL, DMODEL);
}